// round 3
// baseline (speedup 1.0000x reference)
#include <cuda_runtime.h>

#define BB 512
#define SS 512
#define CC 96

typedef unsigned long long u64;

// Scratch (no allocations allowed)
__device__ float g_num[BB];
__device__ float g_den[BB];

// ---- f32x2 packed helpers (Blackwell sm_103a) ----
__device__ __forceinline__ u64 pack2(float x, float y) {
    u64 r;
    asm("mov.b64 %0, {%1, %2};" : "=l"(r) : "r"(__float_as_int(x)), "r"(__float_as_int(y)));
    return r;
}
__device__ __forceinline__ u64 dup2(float v) {
    u64 r;
    int b = __float_as_int(v);
    asm("mov.b64 %0, {%1, %1};" : "=l"(r) : "r"(b));
    return r;
}
__device__ __forceinline__ float2 unpack2(u64 v) {
    int lo, hi;
    asm("mov.b64 {%0, %1}, %2;" : "=r"(lo), "=r"(hi) : "l"(v));
    float2 f; f.x = __int_as_float(lo); f.y = __int_as_float(hi);
    return f;
}
__device__ __forceinline__ void fmadd2(u64& d, u64 a, u64 b) {
    asm("fma.rn.f32x2 %0, %1, %2, %0;" : "+l"(d) : "l"(a), "l"(b));
}

// =====================================================================
// Forward algorithm: one CTA of 96 threads handles 2 batches.
// Thread j owns column j of exp(transitions) in registers.
// alpha recurrence in shifted-exp domain; alpha[0] used as the shift.
// =====================================================================
__global__ __launch_bounds__(CC) void crf_forward_kernel(
    const float* __restrict__ em,
    const int* __restrict__ masks,          // bool materialized as int32
    const float* __restrict__ start,
    const float* __restrict__ endt,
    const float* __restrict__ trans)
{
    const int j = threadIdx.x;
    const int b0 = blockIdx.x * 2;
    const int b1 = b0 + 1;

    __shared__ __align__(16) u64 s_p[CC];
    __shared__ float2 s_a0;

    // exp(transitions[:, j]) into registers (fully unrolled -> register array)
    float c[CC];
#pragma unroll
    for (int i = 0; i < CC; i++) c[i] = __expf(trans[i * CC + j]);

    const float* e0p = em + (size_t)b0 * SS * CC + j;
    const float* e1p = em + (size_t)b1 * SS * CC + j;
    const int* m0p = masks + (size_t)b0 * SS;
    const int* m1p = masks + (size_t)b1 * SS;

    const float st = start[j];
    float ax = st + e0p[0];
    float ay = st + e1p[0];
    if (j == 0) { s_a0.x = ax; s_a0.y = ay; }
    __syncthreads();

    for (int t = 1; t < SS; t++) {
        float2 a0 = s_a0;
        float px = __expf(ax - a0.x);
        float py = __expf(ay - a0.y);
        s_p[j] = pack2(px, py);

        // prefetch next-step operands while p propagates
        float ex = e0p[t * CC];
        float ey = e1p[t * CC];
        int m0 = m0p[t];
        int m1 = m1p[t];
        __syncthreads();

        // q_j = sum_i p_i * expT[i][j], two batches packed, 4 accumulators
        u64 q0 = 0ull, q1 = 0ull, q2 = 0ull, q3 = 0ull;
#pragma unroll
        for (int i = 0; i < CC; i += 4) {
            ulonglong2 pA = *reinterpret_cast<const ulonglong2*>(s_p + i);
            ulonglong2 pB = *reinterpret_cast<const ulonglong2*>(s_p + i + 2);
            fmadd2(q0, pA.x, dup2(c[i + 0]));
            fmadd2(q1, pA.y, dup2(c[i + 1]));
            fmadd2(q2, pB.x, dup2(c[i + 2]));
            fmadd2(q3, pB.y, dup2(c[i + 3]));
        }
        float2 f0 = unpack2(q0), f1 = unpack2(q1), f2 = unpack2(q2), f3 = unpack2(q3);
        float qx = (f0.x + f1.x) + (f2.x + f3.x);
        float qy = (f0.y + f1.y) + (f2.y + f3.y);

        float nx = a0.x + __logf(qx) + ex;
        float ny = a0.y + __logf(qy) + ey;
        ax = m0 ? nx : ax;
        ay = m1 ? ny : ay;

        if (j == 0) { s_a0.x = ax; s_a0.y = ay; }
        __syncthreads();
    }

    // denominator = logsumexp_j(alpha_j + end_j), shifted by alpha[0]
    float2 a0 = s_a0;
    float ej = endt[j];
    s_p[j] = pack2(__expf(ax + ej - a0.x), __expf(ay + ej - a0.y));
    __syncthreads();
    if (j == 0) {
        float sx = 0.f, sy = 0.f;
#pragma unroll
        for (int i = 0; i < CC; i++) {
            float2 f = unpack2(s_p[i]);
            sx += f.x; sy += f.y;
        }
        g_den[b0] = a0.x + __logf(sx);
        g_den[b1] = a0.y + __logf(sy);
    }
}

// =====================================================================
// Numerator: one warp per batch.  tags: int64 in metadata but the
// harness materializes narrow int types as int32 (proven for bool).
// =====================================================================
__global__ void crf_num_kernel(
    const float* __restrict__ em,
    const int* __restrict__ tags,           // int64 materialized as int32
    const int* __restrict__ masks,          // int32 bools
    const float* __restrict__ start,
    const float* __restrict__ endt,
    const float* __restrict__ trans)
{
    int warp = (blockIdx.x * blockDim.x + threadIdx.x) >> 5;
    int lane = threadIdx.x & 31;
    if (warp >= BB) return;

    const int* tg = tags + (size_t)warp * SS;
    const int* mk = masks + (size_t)warp * SS;
    const float* e = em + (size_t)warp * SS * CC;

    float s = 0.f;
    int cnt = 0;
    for (int t = lane; t < SS; t += 32) {
        int tagt = tg[t];
        bool m = (mk[t] != 0);
        cnt += m ? 1 : 0;
        if (t == 0) {
            s += start[tagt] + e[tagt];
        } else if (m) {
            int tp = tg[t - 1];
            s += trans[tp * CC + tagt] + e[(size_t)t * CC + tagt];
        }
    }
#pragma unroll
    for (int o = 16; o; o >>= 1) {
        s += __shfl_xor_sync(0xFFFFFFFFu, s, o);
        cnt += __shfl_xor_sync(0xFFFFFFFFu, cnt, o);
    }
    if (lane == 0) {
        int last = cnt - 1;
        int lt = tg[last];
        g_num[warp] = s + endt[lt];
    }
}

// =====================================================================
// Final mean reduce
// =====================================================================
__global__ void crf_reduce_kernel(float* __restrict__ out)
{
    __shared__ float sh[BB];
    int t = threadIdx.x;
    sh[t] = g_num[t] - g_den[t];
    __syncthreads();
#pragma unroll
    for (int o = BB / 2; o > 0; o >>= 1) {
        if (t < o) sh[t] += sh[t + o];
        __syncthreads();
    }
    if (t == 0) out[0] = sh[0] * (1.0f / (float)BB);
}

extern "C" void kernel_launch(void* const* d_in, const int* in_sizes, int n_in,
                              void* d_out, int out_size)
{
    const float* em    = (const float*)d_in[0];
    const int*   tags  = (const int*)d_in[1];
    const int*   masks = (const int*)d_in[2];
    const float* start = (const float*)d_in[3];
    const float* endt  = (const float*)d_in[4];
    const float* trans = (const float*)d_in[5];
    float* out = (float*)d_out;

    crf_num_kernel<<<BB / 8, 256>>>(em, tags, masks, start, endt, trans);
    crf_forward_kernel<<<BB / 2, CC>>>(em, masks, start, endt, trans);
    crf_reduce_kernel<<<1, BB>>>(out);
}

// round 4
// speedup vs baseline: 1.0008x; 1.0008x over previous
#include <cuda_runtime.h>

#define BB 512
#define SS 512
#define CC 96

typedef unsigned long long u64;

// Scratch (no allocations allowed)
__device__ float g_num[BB];
__device__ float g_den[BB];

// ---- f32x2 packed helpers (Blackwell sm_103a) ----
__device__ __forceinline__ u64 pack2(float x, float y) {
    u64 r;
    asm("mov.b64 %0, {%1, %2};" : "=l"(r) : "r"(__float_as_int(x)), "r"(__float_as_int(y)));
    return r;
}
__device__ __forceinline__ u64 dup2(float v) {
    u64 r;
    int b = __float_as_int(v);
    asm("mov.b64 %0, {%1, %1};" : "=l"(r) : "r"(b));
    return r;
}
__device__ __forceinline__ float2 unpack2(u64 v) {
    int lo, hi;
    asm("mov.b64 {%0, %1}, %2;" : "=r"(lo), "=r"(hi) : "l"(v));
    float2 f; f.x = __int_as_float(lo); f.y = __int_as_float(hi);
    return f;
}
__device__ __forceinline__ void fmadd2(u64& d, u64 a, u64 b) {
    asm("fma.rn.f32x2 %0, %1, %2, %0;" : "+l"(d) : "l"(a), "l"(b));
}

// =====================================================================
// Forward algorithm: one CTA of 96 threads handles 2 batches.
// Thread j owns column j of exp(transitions) in registers.
// alpha recurrence in shifted-exp domain; alpha[0] used as the shift.
// =====================================================================
__global__ __launch_bounds__(CC) void crf_forward_kernel(
    const float* __restrict__ em,
    const int* __restrict__ masks,          // bool materialized as int32
    const float* __restrict__ start,
    const float* __restrict__ endt,
    const float* __restrict__ trans)
{
    const int j = threadIdx.x;
    const int b0 = blockIdx.x * 2;
    const int b1 = b0 + 1;

    __shared__ __align__(16) u64 s_p[CC];
    __shared__ float2 s_a0;

    // exp(transitions[:, j]) into registers (fully unrolled -> register array)
    float c[CC];
#pragma unroll
    for (int i = 0; i < CC; i++) c[i] = __expf(trans[i * CC + j]);

    const float* e0p = em + (size_t)b0 * SS * CC + j;
    const float* e1p = em + (size_t)b1 * SS * CC + j;
    const int* m0p = masks + (size_t)b0 * SS;
    const int* m1p = masks + (size_t)b1 * SS;

    const float st = start[j];
    float ax = st + e0p[0];
    float ay = st + e1p[0];
    if (j == 0) { s_a0.x = ax; s_a0.y = ay; }
    __syncthreads();

    for (int t = 1; t < SS; t++) {
        float2 a0 = s_a0;
        float px = __expf(ax - a0.x);
        float py = __expf(ay - a0.y);
        s_p[j] = pack2(px, py);

        // prefetch next-step operands while p propagates
        float ex = e0p[t * CC];
        float ey = e1p[t * CC];
        int m0 = m0p[t];
        int m1 = m1p[t];
        __syncthreads();

        // q_j = sum_i p_i * expT[i][j], two batches packed, 4 accumulators
        u64 q0 = 0ull, q1 = 0ull, q2 = 0ull, q3 = 0ull;
#pragma unroll
        for (int i = 0; i < CC; i += 4) {
            ulonglong2 pA = *reinterpret_cast<const ulonglong2*>(s_p + i);
            ulonglong2 pB = *reinterpret_cast<const ulonglong2*>(s_p + i + 2);
            fmadd2(q0, pA.x, dup2(c[i + 0]));
            fmadd2(q1, pA.y, dup2(c[i + 1]));
            fmadd2(q2, pB.x, dup2(c[i + 2]));
            fmadd2(q3, pB.y, dup2(c[i + 3]));
        }
        float2 f0 = unpack2(q0), f1 = unpack2(q1), f2 = unpack2(q2), f3 = unpack2(q3);
        float qx = (f0.x + f1.x) + (f2.x + f3.x);
        float qy = (f0.y + f1.y) + (f2.y + f3.y);

        float nx = a0.x + __logf(qx) + ex;
        float ny = a0.y + __logf(qy) + ey;
        ax = m0 ? nx : ax;
        ay = m1 ? ny : ay;

        if (j == 0) { s_a0.x = ax; s_a0.y = ay; }
        __syncthreads();
    }

    // denominator = logsumexp_j(alpha_j + end_j), shifted by alpha[0]
    float2 a0 = s_a0;
    float ej = endt[j];
    s_p[j] = pack2(__expf(ax + ej - a0.x), __expf(ay + ej - a0.y));
    __syncthreads();
    if (j == 0) {
        float sx = 0.f, sy = 0.f;
#pragma unroll
        for (int i = 0; i < CC; i++) {
            float2 f = unpack2(s_p[i]);
            sx += f.x; sy += f.y;
        }
        g_den[b0] = a0.x + __logf(sx);
        g_den[b1] = a0.y + __logf(sy);
    }
}

// =====================================================================
// Numerator: one warp per batch.  tags: int64 in metadata but the
// harness materializes narrow int types as int32 (proven for bool).
// =====================================================================
__global__ void crf_num_kernel(
    const float* __restrict__ em,
    const int* __restrict__ tags,           // int64 materialized as int32
    const int* __restrict__ masks,          // int32 bools
    const float* __restrict__ start,
    const float* __restrict__ endt,
    const float* __restrict__ trans)
{
    int warp = (blockIdx.x * blockDim.x + threadIdx.x) >> 5;
    int lane = threadIdx.x & 31;
    if (warp >= BB) return;

    const int* tg = tags + (size_t)warp * SS;
    const int* mk = masks + (size_t)warp * SS;
    const float* e = em + (size_t)warp * SS * CC;

    float s = 0.f;
    int cnt = 0;
    for (int t = lane; t < SS; t += 32) {
        int tagt = tg[t];
        bool m = (mk[t] != 0);
        cnt += m ? 1 : 0;
        if (t == 0) {
            s += start[tagt] + e[tagt];
        } else if (m) {
            int tp = tg[t - 1];
            s += trans[tp * CC + tagt] + e[(size_t)t * CC + tagt];
        }
    }
#pragma unroll
    for (int o = 16; o; o >>= 1) {
        s += __shfl_xor_sync(0xFFFFFFFFu, s, o);
        cnt += __shfl_xor_sync(0xFFFFFFFFu, cnt, o);
    }
    if (lane == 0) {
        int last = cnt - 1;
        int lt = tg[last];
        g_num[warp] = s + endt[lt];
    }
}

// =====================================================================
// Final mean reduce
// =====================================================================
__global__ void crf_reduce_kernel(float* __restrict__ out)
{
    __shared__ float sh[BB];
    int t = threadIdx.x;
    sh[t] = g_num[t] - g_den[t];
    __syncthreads();
#pragma unroll
    for (int o = BB / 2; o > 0; o >>= 1) {
        if (t < o) sh[t] += sh[t + o];
        __syncthreads();
    }
    if (t == 0) out[0] = sh[0] * (1.0f / (float)BB);
}

extern "C" void kernel_launch(void* const* d_in, const int* in_sizes, int n_in,
                              void* d_out, int out_size)
{
    const float* em    = (const float*)d_in[0];
    const int*   tags  = (const int*)d_in[1];
    const int*   masks = (const int*)d_in[2];
    const float* start = (const float*)d_in[3];
    const float* endt  = (const float*)d_in[4];
    const float* trans = (const float*)d_in[5];
    float* out = (float*)d_out;

    crf_num_kernel<<<BB / 8, 256>>>(em, tags, masks, start, endt, trans);
    crf_forward_kernel<<<BB / 2, CC>>>(em, masks, start, endt, trans);
    crf_reduce_kernel<<<1, BB>>>(out);
}

// round 5
// speedup vs baseline: 1.4399x; 1.4388x over previous
#include <cuda_runtime.h>

#define BB 512
#define SS 512
#define CC 96
#define TEAMS 4
#define FWD_THREADS (TEAMS * CC)   // 384

typedef unsigned long long u64;

__device__ float g_num[BB];
__device__ float g_den[BB];

// ---- f32x2 packed helpers (sm_103a) ----
__device__ __forceinline__ u64 pack2(float x, float y) {
    u64 r;
    asm("mov.b64 %0, {%1, %2};" : "=l"(r) : "r"(__float_as_int(x)), "r"(__float_as_int(y)));
    return r;
}
__device__ __forceinline__ float2 unpack2(u64 v) {
    int lo, hi;
    asm("mov.b64 {%0, %1}, %2;" : "=r"(lo), "=r"(hi) : "l"(v));
    float2 f; f.x = __int_as_float(lo); f.y = __int_as_float(hi);
    return f;
}
__device__ __forceinline__ void fmadd2(u64& d, u64 a, u64 b) {
    asm("fma.rn.f32x2 %0, %1, %2, %0;" : "+l"(d) : "l"(a), "l"(b));
}
__device__ __forceinline__ float fast_rcp(float x) {
    float r;
    asm("rcp.approx.f32 %0, %1;" : "=f"(r) : "f"(x));
    return r;
}

#define TBAR(id) asm volatile("bar.sync %0, %1;" :: "r"(id), "r"(CC) : "memory")

// =====================================================================
// Forward: 128 CTAs x 384 threads. 4 independent teams of 96 threads,
// one batch each, synced via named barriers. Thread j owns column j of
// expT, pre-paired into f32x2 registers. Unnormalized exp-domain
// recurrence: u_j = (sum_i p_i * expT_ij) * exp(em_j);
// p_j = u_j * rcp(u_0); shift -= log(rcp(u_0)). No exp/log on the
// per-thread critical path.
// =====================================================================
__global__ __launch_bounds__(FWD_THREADS) void crf_forward_kernel(
    const float* __restrict__ em,
    const int* __restrict__ masks,
    const float* __restrict__ start,
    const float* __restrict__ endt,
    const float* __restrict__ trans)
{
    const int team = threadIdx.x / CC;
    const int j = threadIdx.x - team * CC;
    const int barid = team + 1;
    const int b = blockIdx.x * TEAMS + team;

    __shared__ __align__(16) float s_p[TEAMS][CC];
    __shared__ float s_r[TEAMS];

    // expT column j, paired over states (2k, 2k+1), resident in registers.
    u64 cpair[CC / 2];
#pragma unroll
    for (int k = 0; k < CC / 2; k++) {
        float c0 = __expf(trans[(2 * k) * CC + j]);
        float c1 = __expf(trans[(2 * k + 1) * CC + j]);
        cpair[k] = pack2(c0, c1);
    }

    const float* emb = em + (size_t)b * SS * CC + j;
    const int* mb = masks + (size_t)b * SS;

    // ---- t = 0 ----
    float a = start[j] + emb[0];
    if (j == 0) s_r[team] = a;
    TBAR(barid);
    float shift = s_r[team];
    float p = __expf(a - shift);
    s_p[team][j] = p;
    TBAR(barid);

    // ---- prefetch pipeline (distance 2) ----
    float E = __expf(emb[1 * CC]);    // exp(em[t]) for t = 1
    int m_cur = mb[1];
    float em_next = emb[2 * CC];      // em[t+1]
    int m_next = mb[2];

    const ulonglong2* pv = reinterpret_cast<const ulonglong2*>(s_p[team]);

    for (int t = 1; t < SS; t++) {
        // issue prefetch for t+2 (clamped)
        int pf = t + 2 < SS ? t + 2 : SS - 1;
        float em_pf = emb[pf * CC];
        int m_pf = mb[pf];

        if (m_cur) {
            // q_j = sum_i p_i * expT[i][j], state-pair packed
            u64 q0 = 0ull, q1 = 0ull;
#pragma unroll
            for (int k = 0; k < CC / 4; k++) {
                ulonglong2 pp = pv[k];
                fmadd2(q0, pp.x, cpair[2 * k]);
                fmadd2(q1, pp.y, cpair[2 * k + 1]);
            }
            float2 f0 = unpack2(q0), f1 = unpack2(q1);
            float q = (f0.x + f0.y) + (f1.x + f1.y);
            float u = q * E;
            if (j == 0) {
                float r0 = fast_rcp(u);
                s_r[team] = r0;
                shift -= __logf(r0);   // exactly consistent with p = u*r0
            }
            TBAR(barid);
            float r = s_r[team];
            p = u * r;
            s_p[team][j] = p;
            TBAR(barid);
        }

        // rotate prefetch registers
        E = __expf(em_next);
        m_cur = m_next;
        em_next = em_pf;
        m_next = m_pf;
    }

    // denominator = shift + log(sum_j p_j * exp(end_j))
    float v = p * __expf(endt[j]);
    s_p[team][j] = v;
    TBAR(barid);
    if (j == 0) {
        float s = 0.f;
#pragma unroll
        for (int i = 0; i < CC; i++) s += s_p[team][i];
        g_den[b] = shift + __logf(s);
    }
}

// =====================================================================
// Numerator: one CTA (128 threads) per batch.
// =====================================================================
__global__ __launch_bounds__(128) void crf_num_kernel(
    const float* __restrict__ em,
    const int* __restrict__ tags,
    const int* __restrict__ masks,
    const float* __restrict__ start,
    const float* __restrict__ endt,
    const float* __restrict__ trans)
{
    const int b = blockIdx.x;
    const int tid = threadIdx.x;
    const int* tg = tags + (size_t)b * SS;
    const int* mk = masks + (size_t)b * SS;
    const float* e = em + (size_t)b * SS * CC;

    float s = 0.f;
    int cnt = 0;
#pragma unroll
    for (int it = 0; it < SS / 128; it++) {
        int t = tid + it * 128;
        int tagt = tg[t];
        int m = mk[t];
        cnt += m ? 1 : 0;
        if (t == 0) {
            s += start[tagt] + e[tagt];
        } else if (m) {
            int tp = tg[t - 1];
            s += trans[tp * CC + tagt] + e[(size_t)t * CC + tagt];
        }
    }
    // warp reduce then cross-warp
    __shared__ float ss[4];
    __shared__ int sc[4];
#pragma unroll
    for (int o = 16; o; o >>= 1) {
        s += __shfl_xor_sync(0xFFFFFFFFu, s, o);
        cnt += __shfl_xor_sync(0xFFFFFFFFu, cnt, o);
    }
    int w = tid >> 5, lane = tid & 31;
    if (lane == 0) { ss[w] = s; sc[w] = cnt; }
    __syncthreads();
    if (tid == 0) {
        float st = ss[0] + ss[1] + ss[2] + ss[3];
        int ct = sc[0] + sc[1] + sc[2] + sc[3];
        int lt = tg[ct - 1];
        g_num[b] = st + endt[lt];
    }
}

// =====================================================================
// Final mean reduce
// =====================================================================
__global__ void crf_reduce_kernel(float* __restrict__ out)
{
    __shared__ float sh[BB];
    int t = threadIdx.x;
    sh[t] = g_num[t] - g_den[t];
    __syncthreads();
#pragma unroll
    for (int o = BB / 2; o > 0; o >>= 1) {
        if (t < o) sh[t] += sh[t + o];
        __syncthreads();
    }
    if (t == 0) out[0] = sh[0] * (1.0f / (float)BB);
}

extern "C" void kernel_launch(void* const* d_in, const int* in_sizes, int n_in,
                              void* d_out, int out_size)
{
    const float* em    = (const float*)d_in[0];
    const int*   tags  = (const int*)d_in[1];
    const int*   masks = (const int*)d_in[2];
    const float* start = (const float*)d_in[3];
    const float* endt  = (const float*)d_in[4];
    const float* trans = (const float*)d_in[5];
    float* out = (float*)d_out;

    crf_num_kernel<<<BB, 128>>>(em, tags, masks, start, endt, trans);
    crf_forward_kernel<<<BB / TEAMS, FWD_THREADS>>>(em, masks, start, endt, trans);
    crf_reduce_kernel<<<1, BB>>>(out);
}

// round 6
// speedup vs baseline: 1.7810x; 1.2369x over previous
#include <cuda_runtime.h>

#define BB 512
#define SS 512
#define CC 96
#define TEAMS 4
#define TEAM_THREADS (CC * 2)              // 192: (j,h) pairs, h in {0,1}
#define FWD_THREADS (TEAMS * TEAM_THREADS) // 768

typedef unsigned long long u64;

__device__ float g_num[BB];
__device__ float g_den[BB];

// ---- f32x2 packed helpers (sm_103a) ----
__device__ __forceinline__ u64 pack2(float x, float y) {
    u64 r;
    asm("mov.b64 %0, {%1, %2};" : "=l"(r) : "r"(__float_as_int(x)), "r"(__float_as_int(y)));
    return r;
}
__device__ __forceinline__ float2 unpack2(u64 v) {
    int lo, hi;
    asm("mov.b64 {%0, %1}, %2;" : "=r"(lo), "=r"(hi) : "l"(v));
    float2 f; f.x = __int_as_float(lo); f.y = __int_as_float(hi);
    return f;
}
__device__ __forceinline__ void fmadd2(u64& d, u64 a, u64 b) {
    asm("fma.rn.f32x2 %0, %1, %2, %0;" : "+l"(d) : "l"(a), "l"(b));
}
__device__ __forceinline__ float fast_rcp(float x) {
    float r;
    asm("rcp.approx.f32 %0, %1;" : "=f"(r) : "f"(x));
    return r;
}

#define TBAR(id) asm volatile("bar.sync %0, %1;" :: "r"(id), "r"(TEAM_THREADS) : "memory")

// =====================================================================
// Forward: 128 CTAs x 768 threads = 4 teams x (96 columns x 2 halves).
// Thread (j,h) owns expT rows [48h, 48h+48) of column j in registers.
// Unnormalized exp domain, normalizer r = rcp(u_prev[0]) computed by
// every h=0 thread locally (off critical path); single barrier per
// step with ping-pong u buffers. shift S tracked by thread (0,0).
// =====================================================================
__global__ __launch_bounds__(FWD_THREADS) void crf_forward_kernel(
    const float* __restrict__ em,
    const int* __restrict__ masks,
    const float* __restrict__ start,
    const float* __restrict__ endt,
    const float* __restrict__ trans)
{
    const int team = threadIdx.x / TEAM_THREADS;
    const int idx  = threadIdx.x - team * TEAM_THREADS;
    const int j = idx >> 1;
    const int h = idx & 1;
    const int barid = team + 1;
    const int b = blockIdx.x * TEAMS + team;

    __shared__ __align__(16) float s_u[2][TEAMS][CC];

    // expT rows [48h, 48h+48) of column j, packed in state-pairs.
    u64 cpair[24];
#pragma unroll
    for (int m = 0; m < 24; m++) {
        float c0 = __expf(trans[(48 * h + 2 * m) * CC + j]);
        float c1 = __expf(trans[(48 * h + 2 * m + 1) * CC + j]);
        cpair[m] = pack2(c0, c1);
    }

    const float* emb = em + (size_t)b * SS * CC + j;
    const int* mb = masks + (size_t)b * SS;

    // ---- t = 0: u = exp(start+em), unshifted (values ~e^±6, safe). S = 0.
    float u = 0.f, S = 0.f;
    if (h == 0) {
        u = __expf(start[j] + emb[0]);
        s_u[0][team][j] = u;
    }

    // prefetch pipeline (distance 2), h=0 lanes only
    float E = 0.f, em_next = 0.f;
    int m_cur = 0, m_next = 0;
    if (h == 0) {
        E = __expf(emb[1 * CC]);
        m_cur = mb[1];
        em_next = emb[2 * CC];
        m_next = mb[2];
    }
    TBAR(barid);

    int p = 0;
    for (int t = 1; t < SS; t++) {
        // normalizer from u_prev[0]: tiny broadcast LDS, rcp hidden under matvec
        float r = fast_rcp(s_u[p][team][0]);

        // prefetch t+2 (h=0)
        float em_pf = 0.f; int m_pf = 0;
        if (h == 0) {
            int pf = t + 2 < SS ? t + 2 : SS - 1;
            em_pf = emb[pf * CC];
            m_pf = mb[pf];
        }

        // partial matvec over 48 states
        const ulonglong2* pv = reinterpret_cast<const ulonglong2*>(&s_u[p][team][h * 48]);
        u64 q0 = 0ull, q1 = 0ull;
#pragma unroll
        for (int k = 0; k < 12; k++) {
            ulonglong2 pp = pv[k];
            fmadd2(q0, pp.x, cpair[2 * k]);
            fmadd2(q1, pp.y, cpair[2 * k + 1]);
        }
        float2 f0 = unpack2(q0), f1 = unpack2(q1);
        float w = (f0.x + f0.y) + (f1.x + f1.y);
        w += __shfl_xor_sync(0xFFFFFFFFu, w, 1);   // combine halves (adjacent lanes)

        if (h == 0) {
            float u_new = w * (E * r);
            u = m_cur ? u_new : u;
            s_u[p ^ 1][team][j] = u;
            if (j == 0) S = m_cur ? S - __logf(r) : S;
            // rotate prefetch
            E = __expf(em_next);
            m_cur = m_next;
            em_next = em_pf;
            m_next = m_pf;
        }
        TBAR(barid);
        p ^= 1;
    }

    // denominator = S + log(sum_j u_j * exp(end_j))
    if (h == 0) s_u[p ^ 1][team][j] = u * __expf(endt[j]);
    TBAR(barid);
    if (idx == 0) {
        float s = 0.f;
#pragma unroll
        for (int i = 0; i < CC; i++) s += s_u[p ^ 1][team][i];
        g_den[b] = S + __logf(s);
    }
}

// =====================================================================
// Numerator: one CTA (128 threads) per batch.
// =====================================================================
__global__ __launch_bounds__(128) void crf_num_kernel(
    const float* __restrict__ em,
    const int* __restrict__ tags,
    const int* __restrict__ masks,
    const float* __restrict__ start,
    const float* __restrict__ endt,
    const float* __restrict__ trans)
{
    const int b = blockIdx.x;
    const int tid = threadIdx.x;
    const int* tg = tags + (size_t)b * SS;
    const int* mk = masks + (size_t)b * SS;
    const float* e = em + (size_t)b * SS * CC;

    float s = 0.f;
    int cnt = 0;
#pragma unroll
    for (int it = 0; it < SS / 128; it++) {
        int t = tid + it * 128;
        int tagt = tg[t];
        int m = mk[t];
        cnt += m ? 1 : 0;
        if (t == 0) {
            s += start[tagt] + e[tagt];
        } else if (m) {
            int tp = tg[t - 1];
            s += trans[tp * CC + tagt] + e[(size_t)t * CC + tagt];
        }
    }
    __shared__ float ss[4];
    __shared__ int sc[4];
#pragma unroll
    for (int o = 16; o; o >>= 1) {
        s += __shfl_xor_sync(0xFFFFFFFFu, s, o);
        cnt += __shfl_xor_sync(0xFFFFFFFFu, cnt, o);
    }
    int w = tid >> 5, lane = tid & 31;
    if (lane == 0) { ss[w] = s; sc[w] = cnt; }
    __syncthreads();
    if (tid == 0) {
        float st = ss[0] + ss[1] + ss[2] + ss[3];
        int ct = sc[0] + sc[1] + sc[2] + sc[3];
        int lt = tg[ct - 1];
        g_num[b] = st + endt[lt];
    }
}

// =====================================================================
// Final mean reduce
// =====================================================================
__global__ void crf_reduce_kernel(float* __restrict__ out)
{
    __shared__ float sh[BB];
    int t = threadIdx.x;
    sh[t] = g_num[t] - g_den[t];
    __syncthreads();
#pragma unroll
    for (int o = BB / 2; o > 0; o >>= 1) {
        if (t < o) sh[t] += sh[t + o];
        __syncthreads();
    }
    if (t == 0) out[0] = sh[0] * (1.0f / (float)BB);
}

extern "C" void kernel_launch(void* const* d_in, const int* in_sizes, int n_in,
                              void* d_out, int out_size)
{
    const float* em    = (const float*)d_in[0];
    const int*   tags  = (const int*)d_in[1];
    const int*   masks = (const int*)d_in[2];
    const float* start = (const float*)d_in[3];
    const float* endt  = (const float*)d_in[4];
    const float* trans = (const float*)d_in[5];
    float* out = (float*)d_out;

    crf_forward_kernel<<<BB / TEAMS, FWD_THREADS>>>(em, masks, start, endt, trans);
    crf_num_kernel<<<BB, 128>>>(em, tags, masks, start, endt, trans);
    crf_reduce_kernel<<<1, BB>>>(out);
}

// round 7
// speedup vs baseline: 2.5510x; 1.4323x over previous
#include <cuda_runtime.h>

#define BB 512
#define SS 512
#define CC 96
#define TEAMS 4
#define TEAM_THREADS CC                      // 96 threads per team
#define FWD_THREADS (TEAMS * TEAM_THREADS)   // 384

typedef unsigned long long u64;

__device__ float g_num[BB];
__device__ float g_den[BB];

// ---- f32x2 packed helpers (sm_103a) ----
__device__ __forceinline__ u64 pack2(float x, float y) {
    u64 r;
    asm("mov.b64 %0, {%1, %2};" : "=l"(r) : "r"(__float_as_int(x)), "r"(__float_as_int(y)));
    return r;
}
__device__ __forceinline__ float2 unpack2(u64 v) {
    int lo, hi;
    asm("mov.b64 {%0, %1}, %2;" : "=r"(lo), "=r"(hi) : "l"(v));
    float2 f; f.x = __int_as_float(lo); f.y = __int_as_float(hi);
    return f;
}
__device__ __forceinline__ void fmadd2(u64& d, u64 a, u64 b) {
    asm("fma.rn.f32x2 %0, %1, %2, %0;" : "+l"(d) : "l"(a), "l"(b));
}
__device__ __forceinline__ float fast_rcp(float x) {
    float r;
    asm("rcp.approx.f32 %0, %1;" : "=f"(r) : "f"(x));
    return r;
}

#define TBAR(id) asm volatile("bar.sync %0, %1;" :: "r"(id), "r"(TEAM_THREADS) : "memory")

// =====================================================================
// Forward: 128 CTAs x 384 threads = 4 teams x 96.
// Thread idx: jj = idx>>1 (column pair {2jj, 2jj+1}), h = idx&1 (K half).
// 12 LDS.128 feed 48 FFMA2 (2 columns x 24). One shfl.xor(1) swaps the
// cross partials so each thread finalizes exactly column idx.
// Unnormalized exp domain; r = rcp(u_prev[0]) local everywhere; exact
// shift tracking S -= log(r) on thread 0. Single barrier + ping-pong.
// =====================================================================
__global__ __launch_bounds__(FWD_THREADS, 1) void crf_forward_kernel(
    const float* __restrict__ em,
    const int* __restrict__ masks,
    const float* __restrict__ start,
    const float* __restrict__ endt,
    const float* __restrict__ trans)
{
    const int team = threadIdx.x / TEAM_THREADS;
    const int idx  = threadIdx.x - team * TEAM_THREADS;   // 0..95, own column
    const int jj = idx >> 1;
    const int h  = idx & 1;
    const int barid = team + 1;
    const int b = blockIdx.x * TEAMS + team;

    __shared__ __align__(16) float s_u[2][TEAMS][CC];

    // Coefficients: expT rows [48h,48h+48) for columns 2jj and 2jj+1,
    // packed over state pairs. 48 u64 in registers.
    u64 cA[24], cB[24];
    const int colA = 2 * jj, colB = 2 * jj + 1;
#pragma unroll
    for (int m = 0; m < 24; m++) {
        int row = 48 * h + 2 * m;
        cA[m] = pack2(__expf(trans[row * CC + colA]), __expf(trans[(row + 1) * CC + colA]));
        cB[m] = pack2(__expf(trans[row * CC + colB]), __expf(trans[(row + 1) * CC + colB]));
    }

    const float* emb = em + (size_t)b * SS * CC + idx;
    const int* mb = masks + (size_t)b * SS;

    // ---- t = 0 ----
    float u = __expf(start[idx] + emb[0]);
    float S = 0.f;
    s_u[0][team][idx] = u;

    // prefetch pipeline (distance 2)
    float E = __expf(emb[1 * CC]);
    int m_cur = mb[1];
    float em_next = emb[2 * CC];
    int m_next = mb[2];
    TBAR(barid);

    int p = 0;
    for (int t = 1; t < SS; t++) {
        float r = fast_rcp(s_u[p][team][0]);

        int pf = t + 2 < SS ? t + 2 : SS - 1;
        float em_pf = emb[pf * CC];
        int m_pf = mb[pf];

        // partial matvec: 48 states (half h) x 2 columns, shared LDS.128
        const ulonglong2* pv = reinterpret_cast<const ulonglong2*>(&s_u[p][team][h * 48]);
        u64 qA0 = 0ull, qA1 = 0ull, qB0 = 0ull, qB1 = 0ull;
#pragma unroll
        for (int k = 0; k < 12; k++) {
            ulonglong2 pp = pv[k];
            fmadd2(qA0, pp.x, cA[2 * k]);
            fmadd2(qA1, pp.y, cA[2 * k + 1]);
            fmadd2(qB0, pp.x, cB[2 * k]);
            fmadd2(qB1, pp.y, cB[2 * k + 1]);
        }
        float2 fa0 = unpack2(qA0), fa1 = unpack2(qA1);
        float2 fb0 = unpack2(qB0), fb1 = unpack2(qB1);
        float wA = (fa0.x + fa0.y) + (fa1.x + fa1.y);
        float wB = (fb0.x + fb0.y) + (fb1.x + fb1.y);

        // I finalize column idx (= 2jj+h); partner idx^1 holds its other half.
        float mine  = h ? wB : wA;
        float other = h ? wA : wB;
        float q = mine + __shfl_xor_sync(0xFFFFFFFFu, other, 1);

        float u_new = q * (E * r);
        u = m_cur ? u_new : u;
        s_u[p ^ 1][team][idx] = u;
        if (idx == 0) S = m_cur ? S - __logf(r) : S;

        // rotate prefetch
        E = __expf(em_next);
        m_cur = m_next;
        em_next = em_pf;
        m_next = m_pf;

        TBAR(barid);
        p ^= 1;
    }

    // denominator = S + log(sum_j u_j * exp(end_j))
    s_u[p][team][idx] = u * __expf(endt[idx]);
    TBAR(barid);
    if (idx == 0) {
        float s = 0.f;
#pragma unroll
        for (int i = 0; i < CC; i++) s += s_u[p][team][i];
        g_den[b] = S + __logf(s);
    }
}

// =====================================================================
// Numerator: one CTA (128 threads) per batch.
// =====================================================================
__global__ __launch_bounds__(128) void crf_num_kernel(
    const float* __restrict__ em,
    const int* __restrict__ tags,
    const int* __restrict__ masks,
    const float* __restrict__ start,
    const float* __restrict__ endt,
    const float* __restrict__ trans)
{
    const int b = blockIdx.x;
    const int tid = threadIdx.x;
    const int* tg = tags + (size_t)b * SS;
    const int* mk = masks + (size_t)b * SS;
    const float* e = em + (size_t)b * SS * CC;

    float s = 0.f;
    int cnt = 0;
#pragma unroll
    for (int it = 0; it < SS / 128; it++) {
        int t = tid + it * 128;
        int tagt = tg[t];
        int m = mk[t];
        cnt += m ? 1 : 0;
        if (t == 0) {
            s += start[tagt] + e[tagt];
        } else if (m) {
            int tp = tg[t - 1];
            s += trans[tp * CC + tagt] + e[(size_t)t * CC + tagt];
        }
    }
    __shared__ float ss[4];
    __shared__ int sc[4];
#pragma unroll
    for (int o = 16; o; o >>= 1) {
        s += __shfl_xor_sync(0xFFFFFFFFu, s, o);
        cnt += __shfl_xor_sync(0xFFFFFFFFu, cnt, o);
    }
    int w = tid >> 5, lane = tid & 31;
    if (lane == 0) { ss[w] = s; sc[w] = cnt; }
    __syncthreads();
    if (tid == 0) {
        float st = ss[0] + ss[1] + ss[2] + ss[3];
        int ct = sc[0] + sc[1] + sc[2] + sc[3];
        int lt = tg[ct - 1];
        g_num[b] = st + endt[lt];
    }
}

// =====================================================================
// Final mean reduce
// =====================================================================
__global__ void crf_reduce_kernel(float* __restrict__ out)
{
    __shared__ float sh[BB];
    int t = threadIdx.x;
    sh[t] = g_num[t] - g_den[t];
    __syncthreads();
#pragma unroll
    for (int o = BB / 2; o > 0; o >>= 1) {
        if (t < o) sh[t] += sh[t + o];
        __syncthreads();
    }
    if (t == 0) out[0] = sh[0] * (1.0f / (float)BB);
}

extern "C" void kernel_launch(void* const* d_in, const int* in_sizes, int n_in,
                              void* d_out, int out_size)
{
    const float* em    = (const float*)d_in[0];
    const int*   tags  = (const int*)d_in[1];
    const int*   masks = (const int*)d_in[2];
    const float* start = (const float*)d_in[3];
    const float* endt  = (const float*)d_in[4];
    const float* trans = (const float*)d_in[5];
    float* out = (float*)d_out;

    crf_forward_kernel<<<BB / TEAMS, FWD_THREADS>>>(em, masks, start, endt, trans);
    crf_num_kernel<<<BB, 128>>>(em, tags, masks, start, endt, trans);
    crf_reduce_kernel<<<1, BB>>>(out);
}